// round 13
// baseline (speedup 1.0000x reference)
#include <cuda_runtime.h>
#include <cstdint>

#define DIMD 2048
#define NC 12
#define NC2 144
#define ROWS 128
#define NCTA 256
#define THREADS 512
#define DC 128
#define NCH 16
#define STRA 144
#define STRB 144
#define EPSV 1e-5f

// ---- gil smem byte layout ----
#define OFF_CT 0                       // Ct [128][144] tf32 (73728 B)
#define OFF_B0 73728                   // WiT buf0 [128][144w] (73728 B)
#define OFF_B1 147456                  // WiT buf1 (73728 B)
#define OFF_PV 147456                  // PV staging [128][24]f (aliases B1; dead by c=0)
#define SMEM_BYTES 221184
#define FOFF_PV (OFF_PV / 4)

// ---- pv smem byte layout ----
#define PV_AX0 0                       // x fp32 [64][68w] (17408 B)
#define PV_AX1 17408
#define PV_AW0 34816                   // Wt tf32 [32][76w] (9728 B)
#define PV_AW1 44544
#define PV_SMEM 54272

__device__ __align__(16) uint32_t g_WiT[DIMD * NC2];  // [pos][perm(k)] tf32
__device__ __align__(16) uint32_t g_WT[32 * DIMD];    // [n][k] tf32 (pos|vel|pad)
__device__ __align__(16) float g_PV[32768 * 24];      // pos/vel + bias

__device__ __forceinline__ uint32_t smem_u32(const void* p) {
    uint32_t a;
    asm("{ .reg .u64 t; cvta.to.shared.u64 t, %1; cvt.u32.u64 %0, t; }"
        : "=r"(a) : "l"(p));
    return a;
}
__device__ __forceinline__ uint32_t to_tf32(float x) {
    uint32_t t;
    asm("cvt.rna.tf32.f32 %0, %1;" : "=r"(t) : "f"(x));
    return t;
}
// k16-block permutation: lane tg owns 4 contiguous words = frags for 2 k8 steps
__device__ __forceinline__ int kperm(int k) {
    return (k & ~15) + ((k & 3) << 2) + ((k & 15) >> 2);
}
// n-permutation within each 32-col group (epilogue float4 contiguity)
__device__ __forceinline__ int nperm(int p) {
    int nt = p >> 3, tg = (p >> 1) & 3, j = p & 1;
    return ((nt >> 1) << 4) + ((nt & 1) << 1) + (tg << 2) + j;
}
__device__ __forceinline__ void mma_tf32(float& c0, float& c1, float& c2, float& c3,
                                         uint32_t a0, uint32_t a1, uint32_t a2,
                                         uint32_t a3, uint32_t b0, uint32_t b1) {
    asm volatile(
        "mma.sync.aligned.m16n8k8.row.col.f32.tf32.tf32.f32 "
        "{%0,%1,%2,%3},{%4,%5,%6,%7},{%8,%9},{%0,%1,%2,%3};"
        : "+f"(c0), "+f"(c1), "+f"(c2), "+f"(c3)
        : "r"(a0), "r"(a1), "r"(a2), "r"(a3), "r"(b0), "r"(b1));
}
__device__ __forceinline__ void cpa16(uint32_t dst, const void* src) {
    asm volatile("cp.async.ca.shared.global [%0], [%1], 16;"
                 :: "r"(dst), "l"(src) : "memory");
}

// ---- pre-kernels ----
__global__ void wit_kernel(const float* __restrict__ Wi) {
    int idx = blockIdx.x * 256 + threadIdx.x;  // 144*2048
    int k = idx >> 11;
    int pos = idx & 2047;
    int nsrc = (pos & ~31) + nperm(pos & 31);
    g_WiT[pos * NC2 + kperm(k)] = to_tf32(Wi[k * DIMD + nsrc]);
}
__global__ void wt_kernel(const float* __restrict__ Wp, const float* __restrict__ Wv) {
    int idx = blockIdx.x * 256 + threadIdx.x;  // 32*2048
    int n = idx >> 11;
    int k = idx & 2047;
    float v = 0.f;
    if (n < NC) v = Wp[k * NC + n];
    else if (n < 2 * NC) v = Wv[k * NC + n - NC];
    g_WT[idx] = to_tf32(v);
}

// ---- pv_kernel: PV = x @ [Wp|Wv] + bias (tf32 MMA, 4 CTAs/SM) ----
__global__ __launch_bounds__(128)
void pv_kernel(const float* __restrict__ x, const float* __restrict__ bp,
               const float* __restrict__ bv) {
    extern __shared__ char smc[];
    const int tid = threadIdx.x;
    const int w = tid >> 5, lane = tid & 31;
    const int gq = lane >> 2, tg = lane & 3;
    const int rb = blockIdx.x * 64;
    const uint32_t sb = smem_u32(smc);

    // stage kc=0
#pragma unroll
    for (int j = 0; j < 8; j++) {
        int gi = tid + 128 * j;  // < 1024
        int r = gi >> 4, kq = gi & 15;
        cpa16(sb + PV_AX0 + r * 272 + kq * 16, x + (rb + r) * DIMD + kq * 4);
    }
#pragma unroll
    for (int j = 0; j < 4; j++) {
        int gi = tid + 128 * j;  // < 512
        int n = gi >> 4, kq = gi & 15;
        cpa16(sb + PV_AW0 + n * 304 + kq * 16, g_WT + n * DIMD + kq * 4);
    }
    asm volatile("cp.async.commit_group;" ::: "memory");

    float pa[4][4];
#pragma unroll
    for (int nt = 0; nt < 4; nt++)
#pragma unroll
        for (int q = 0; q < 4; q++) pa[nt][q] = 0.f;

    for (int kc = 0; kc < DIMD / 64; kc++) {
        if (kc < DIMD / 64 - 1) {
            int kn = kc + 1;
            uint32_t axd = (kn & 1) ? PV_AX1 : PV_AX0;
            uint32_t awd = (kn & 1) ? PV_AW1 : PV_AW0;
#pragma unroll
            for (int j = 0; j < 8; j++) {
                int gi = tid + 128 * j;
                int r = gi >> 4, kq = gi & 15;
                cpa16(sb + axd + r * 272 + kq * 16,
                      x + (rb + r) * DIMD + kn * 64 + kq * 4);
            }
#pragma unroll
            for (int j = 0; j < 4; j++) {
                int gi = tid + 128 * j;
                int n = gi >> 4, kq = gi & 15;
                cpa16(sb + awd + n * 304 + kq * 16,
                      g_WT + n * DIMD + kn * 64 + kq * 4);
            }
            asm volatile("cp.async.commit_group;" ::: "memory");
            asm volatile("cp.async.wait_group 1;" ::: "memory");
        } else {
            asm volatile("cp.async.wait_group 0;" ::: "memory");
        }
        __syncthreads();

        const float* X = (const float*)(smc + ((kc & 1) ? PV_AX1 : PV_AX0));
        const uint32_t* WT = (const uint32_t*)(smc + ((kc & 1) ? PV_AW1 : PV_AW0));
#pragma unroll
        for (int k8 = 0; k8 < 8; k8++) {
            const float* Xr = X + (w * 16 + gq) * 68 + k8 * 8 + tg;
            uint32_t a0 = to_tf32(Xr[0]);
            uint32_t a2 = to_tf32(Xr[4]);
            uint32_t a1 = to_tf32(Xr[8 * 68]);
            uint32_t a3 = to_tf32(Xr[8 * 68 + 4]);
#pragma unroll
            for (int nt = 0; nt < 4; nt++) {
                uint32_t b0 = WT[(nt * 8 + gq) * 76 + k8 * 8 + tg];
                uint32_t b1 = WT[(nt * 8 + gq) * 76 + k8 * 8 + tg + 4];
                mma_tf32(pa[nt][0], pa[nt][1], pa[nt][2], pa[nt][3],
                         a0, a1, a2, a3, b0, b1);
            }
        }
        __syncthreads();
    }
    // epilogue: bias + store (cols 0..23; nt=3 is padding)
#pragma unroll
    for (int nt = 0; nt < 3; nt++) {
        int c = nt * 8 + 2 * tg;
        float b0 = (c < NC) ? bp[c] : bv[c - NC];
        float b1 = (c + 1 < NC) ? bp[c + 1] : bv[c + 1 - NC];
        int row = rb + w * 16 + gq;
        *(float2*)(g_PV + row * 24 + c) = make_float2(pa[nt][0] + b0, pa[nt][1] + b1);
        *(float2*)(g_PV + (row + 8) * 24 + c) =
            make_float2(pa[nt][2] + b0, pa[nt][3] + b1);
    }
}

// ---- lnres_kernel: y = inter + x + bi ; LayerNorm ; store ----
__global__ __launch_bounds__(256)
void lnres_kernel(const float* __restrict__ x, const float* __restrict__ bi,
                  const float* __restrict__ gamma, const float* __restrict__ beta,
                  float* __restrict__ out) {
    int warp = threadIdx.x >> 5, lane = threadIdx.x & 31;
    int row = blockIdx.x * 8 + warp;
    const float4* ip = (const float4*)(out + row * DIMD);
    const float4* xp = (const float4*)(x + row * DIMD);
    const float4* bp4 = (const float4*)bi;
    float4 y[16];
    float s = 0.f, q = 0.f;
#pragma unroll
    for (int it = 0; it < 16; it++) {
        int c4 = it * 32 + lane;
        float4 iv = ip[c4];
        float4 xv = xp[c4];
        float4 bv = bp4[c4];
        y[it].x = iv.x + xv.x + bv.x;
        y[it].y = iv.y + xv.y + bv.y;
        y[it].z = iv.z + xv.z + bv.z;
        y[it].w = iv.w + xv.w + bv.w;
        s += (y[it].x + y[it].y) + (y[it].z + y[it].w);
        q += y[it].x * y[it].x + y[it].y * y[it].y + y[it].z * y[it].z +
             y[it].w * y[it].w;
    }
#pragma unroll
    for (int off = 16; off >= 1; off >>= 1) {
        s += __shfl_xor_sync(0xffffffffu, s, off);
        q += __shfl_xor_sync(0xffffffffu, q, off);
    }
    float mu = s * (1.0f / DIMD);
    float rs = rsqrtf(q * (1.0f / DIMD) - mu * mu + EPSV);
    float4* op = (float4*)(out + row * DIMD);
#pragma unroll
    for (int it = 0; it < 16; it++) {
        int c4 = it * 32 + lane;
        float4 g4 = ((const float4*)gamma)[c4];
        float4 b4 = ((const float4*)beta)[c4];
        float4 o;
        o.x = (y[it].x - mu) * rs * g4.x + b4.x;
        o.y = (y[it].y - mu) * rs * g4.y + b4.y;
        o.z = (y[it].z - mu) * rs * g4.z + b4.z;
        o.w = (y[it].w - mu) * rs * g4.w + b4.w;
        op[c4] = o;
    }
}

// ---- gil_kernel: inter = outer(PV) @ WiT (pure GEMM, 128 rows/CTA) ----
__global__ __launch_bounds__(THREADS, 1)
void gil_kernel(float* __restrict__ out) {
    extern __shared__ char smc[];
    float* smf = (float*)smc;
    uint32_t* smu = (uint32_t*)smc;
    const int tid = threadIdx.x;
    const int w = tid >> 5, lane = tid & 31;
    const int gq = lane >> 2, tg = lane & 3;
    const int rowbase = blockIdx.x * ROWS;
    const uint32_t smem_base = smem_u32(smc);

    // chunk-0 prefetch into B0 (group 0)
    {
        const char* src = (const char*)g_WiT;
#pragma unroll
        for (int j = 0; j < 9; j++) {
            int e = (tid + THREADS * j) * 16;  // < 73728
            cpa16(smem_base + OFF_B0 + e, src + e);
        }
        asm volatile("cp.async.commit_group;" ::: "memory");
    }
    // load PV rows into smem (aliases B1; dead once chunk1 prefetch starts)
    {
        const float4* pv4 = (const float4*)(g_PV + rowbase * 24);
        float4* sPV4 = (float4*)(smc + OFF_PV);
#pragma unroll
        for (int j = 0; j < 2; j++) {
            int i = tid + THREADS * j;
            if (i < 768) sPV4[i] = pv4[i];
        }
    }
    __syncthreads();

    // Phase B: Ct[row][perm(k)] = pos_i * vel_j
#pragma unroll
    for (int qit = 0; qit < 36; qit++) {
        int t = tid + THREADS * qit;  // < 18432
        int row = t / NC2;
        int k = t - row * NC2;
        int i = k / NC, j = k - i * NC;
        float ct = smf[FOFF_PV + row * 24 + i] * smf[FOFF_PV + row * 24 + NC + j];
        smu[row * STRA + kperm(k)] = to_tf32(ct);
    }
    __syncthreads();  // Ct visible; PV consumed

    const int rg = w & 7;   // rowgroup: 16 rows
    const int cg = w >> 3;  // colgroup: 64 cols
    const int rowA = rowbase + rg * 16 + gq;
    const int rowB = rowA + 8;
    const uint32_t* A0 = smu + (rg * 16 + gq) * STRA + 4 * tg;
    const uint32_t* A1 = A0 + 8 * STRA;

    for (int c = 0; c < NCH; c++) {
        if (c < NCH - 1) {
            const char* src = (const char*)g_WiT + (c + 1) * DC * NC2 * 4;
            uint32_t bufoff = ((c + 1) & 1) ? OFF_B1 : OFF_B0;
#pragma unroll
            for (int j = 0; j < 9; j++) {
                int e = (tid + THREADS * j) * 16;
                cpa16(smem_base + bufoff + e, src + e);
            }
            asm volatile("cp.async.commit_group;" ::: "memory");
            asm volatile("cp.async.wait_group 1;" ::: "memory");
        } else {
            asm volatile("cp.async.wait_group 0;" ::: "memory");
        }
        __syncthreads();  // chunk c copies from ALL threads visible

        const uint32_t* Bb = smu + ((c & 1) ? OFF_B1 : OFF_B0) / 4 +
                             (cg * 64 + gq) * STRB + 4 * tg;
        float acc[8][4];
#pragma unroll
        for (int nt = 0; nt < 8; nt++)
#pragma unroll
            for (int q = 0; q < 4; q++) acc[nt][q] = 0.f;

#pragma unroll
        for (int k16 = 0; k16 < 9; k16++) {
            uint4 aA = *(const uint4*)(A0 + k16 * 16);
            uint4 aB = *(const uint4*)(A1 + k16 * 16);
#pragma unroll
            for (int nt = 0; nt < 8; nt++) {
                uint4 b = *(const uint4*)(Bb + nt * 8 * STRB + k16 * 16);
                mma_tf32(acc[nt][0], acc[nt][1], acc[nt][2], acc[nt][3],
                         aA.x, aB.x, aA.y, aB.y, b.x, b.y);
                mma_tf32(acc[nt][0], acc[nt][1], acc[nt][2], acc[nt][3],
                         aA.z, aB.z, aA.w, aB.w, b.z, b.w);
            }
        }

        // epilogue: store raw inter (float4, via n-perm layout)
        int cbase = c * DC + cg * 64;
#pragma unroll
        for (int u = 0; u < 4; u++) {
            int col = cbase + 4 * tg + u * 16;
            int n0 = 2 * u;
            float4 va, vb;
            va.x = acc[n0][0];
            va.y = acc[n0][1];
            va.z = acc[n0 + 1][0];
            va.w = acc[n0 + 1][1];
            vb.x = acc[n0][2];
            vb.y = acc[n0][3];
            vb.z = acc[n0 + 1][2];
            vb.w = acc[n0 + 1][3];
            *(float4*)(out + rowA * DIMD + col) = va;
            *(float4*)(out + rowB * DIMD + col) = vb;
        }
        __syncthreads();  // done reading buf[c&1] before next prefetch
    }
}

extern "C" void kernel_launch(void* const* d_in, const int* in_sizes, int n_in,
                              void* d_out, int out_size) {
    const float* x     = (const float*)d_in[0];
    const float* Wp    = (const float*)d_in[1];
    const float* bp    = (const float*)d_in[2];
    const float* Wv    = (const float*)d_in[3];
    const float* bv    = (const float*)d_in[4];
    const float* Wi    = (const float*)d_in[5];
    const float* bi    = (const float*)d_in[6];
    const float* gamma = (const float*)d_in[7];
    const float* beta  = (const float*)d_in[8];
    float* out = (float*)d_out;

    wit_kernel<<<(DIMD * NC2) / 256, 256>>>(Wi);
    wt_kernel<<<(32 * DIMD) / 256, 256>>>(Wp, Wv);
    cudaFuncSetAttribute(pv_kernel, cudaFuncAttributeMaxDynamicSharedMemorySize,
                         PV_SMEM);
    pv_kernel<<<512, 128, PV_SMEM>>>(x, bp, bv);
    cudaFuncSetAttribute(gil_kernel, cudaFuncAttributeMaxDynamicSharedMemorySize,
                         SMEM_BYTES);
    gil_kernel<<<NCTA, THREADS, SMEM_BYTES>>>(out);
    lnres_kernel<<<32768 / 8, 256>>>(x, bi, gamma, beta, out);
}